// round 15
// baseline (speedup 1.0000x reference)
#include <cuda_runtime.h>
#include <cuda_fp16.h>
#include <cstdint>

// Sinkhorn, linear domain, fp16-compressed kernel matrix, stage-buffered
// column sums. Persistent-kernel main loop (one launch for 9 passes, counted
// grid barriers, per-stage work-stealing job queues; all counters zeroed per
// replay by init_kernel).
//   K = valid ? fp16(exp(m)) : 0      (built fused with Sinkhorn step 1, v0=1)
//   step t: u_i = 1 / sum_j K_ij * inv(sb[t-1]_j) ; sb[t]_j += sum_i K_ij u_i
//   sb[9] is inverted in place at the end of the persistent kernel, so
//   final is pure multiplies: out = valid ? u_i * exp(m_ij) * v_j : 0.

#define BB 64
#define NN 1024
#define MM 1024
#define NSTAGE 10

__device__ __half g_K[(size_t)BB * NN * MM];     // 128 MB scratch
__device__ float  g_u[BB * NN];
__device__ float  g_sb[NSTAGE][BB * MM];         // per-stage col-sum buffers
__device__ int    g_barcnt[16];                  // grid-barrier counters
__device__ int    g_jobctr[16];                  // per-stage work-steal counters

// ---------------------------------------------------------------------------
// Zero stage buffers + counters (once per replay). grid=160, blk=256.
// ---------------------------------------------------------------------------
__global__ void init_kernel() {
    float4* p = reinterpret_cast<float4*>(&g_sb[0][0]);
    int idx = blockIdx.x * blockDim.x + threadIdx.x;
    const int total = NSTAGE * BB * MM / 4;
    #pragma unroll
    for (int r = 0; r < 4; r++) {
        int q = idx + r * 40960;
        if (q < total) p[q] = make_float4(0.f, 0.f, 0.f, 0.f);
    }
    if (idx < 16) { g_barcnt[idx] = 0; g_jobctr[idx] = 0; }
}

// ---------------------------------------------------------------------------
// Build + Sinkhorn step 1 (v0 = 1): block = 32 rows x 8 warps x 4 rows.
// exp(m) masked -> fp16 K (zero-padded to 128-col tile boundary), row sums
// -> u1, col partials -> g_sb[0]. grid = (32, 64), block = 256.
// ---------------------------------------------------------------------------
__global__ void __launch_bounds__(256) build_fused_kernel(const float* __restrict__ m,
                                                          const int* __restrict__ nrows,
                                                          const int* __restrict__ ncols) {
    int b  = blockIdx.y;
    int nr = nrows[b];
    int nc = ncols[b];
    int i0 = blockIdx.x * 32;
    if (i0 >= nr || nc == 0) return;
    int npass = (nc + 127) >> 7;

    int lane = threadIdx.x & 31;
    int w    = threadIdx.x >> 5;

    float acc[32];
    #pragma unroll
    for (int k = 0; k < 32; k++) acc[k] = 0.f;

    const float* mb = m + ((size_t)b << 20);
    __half*      Kb = g_K + ((size_t)b << 20);

    #pragma unroll
    for (int q = 0; q < 4; q++) {
        int i = i0 + w * 4 + q;
        if (i < nr) {
            const float* mrow = mb + ((size_t)i << 10);
            __half*      krow = Kb + ((size_t)i << 10);
            uint2 kk[8];
            float s0 = 0.f, s1 = 0.f, s2 = 0.f, s3 = 0.f;
            #pragma unroll
            for (int p = 0; p < 8; p++) {
                if (p < npass) {
                    int j = p * 128 + lane * 4;
                    float4 mv = *reinterpret_cast<const float4*>(mrow + j);
                    float e0 = (j + 0 < nc) ? __expf(mv.x) : 0.f;
                    float e1 = (j + 1 < nc) ? __expf(mv.y) : 0.f;
                    float e2 = (j + 2 < nc) ? __expf(mv.z) : 0.f;
                    float e3 = (j + 3 < nc) ? __expf(mv.w) : 0.f;
                    __half2 h0 = __floats2half2_rn(e0, e1);
                    __half2 h1 = __floats2half2_rn(e2, e3);
                    kk[p].x = *reinterpret_cast<uint32_t*>(&h0);
                    kk[p].y = *reinterpret_cast<uint32_t*>(&h1);
                    *reinterpret_cast<uint2*>(krow + j) = kk[p];
                } else {
                    kk[p] = make_uint2(0u, 0u);
                }
                float2 f0 = __half22float2(*reinterpret_cast<__half2*>(&kk[p].x));
                float2 f1 = __half22float2(*reinterpret_cast<__half2*>(&kk[p].y));
                s0 += f0.x; s1 += f0.y; s2 += f1.x; s3 += f1.y;   // v0 = 1
            }
            float sum = (s0 + s1) + (s2 + s3);
            #pragma unroll
            for (int o = 16; o; o >>= 1) sum += __shfl_xor_sync(0xffffffffu, sum, o);
            float u = (sum > 0.f) ? __fdividef(1.0f, sum) : 0.f;
            if (lane == 0) g_u[(b << 10) + i] = u;
            #pragma unroll
            for (int p = 0; p < 8; p++) {
                float2 f0 = __half22float2(*reinterpret_cast<__half2*>(&kk[p].x));
                float2 f1 = __half22float2(*reinterpret_cast<__half2*>(&kk[p].y));
                acc[p * 4 + 0] = fmaf(f0.x, u, acc[p * 4 + 0]);
                acc[p * 4 + 1] = fmaf(f0.y, u, acc[p * 4 + 1]);
                acc[p * 4 + 2] = fmaf(f1.x, u, acc[p * 4 + 2]);
                acc[p * 4 + 3] = fmaf(f1.y, u, acc[p * 4 + 3]);
            }
        }
    }
    __shared__ float sm[8 * 1024];
    #pragma unroll
    for (int p = 0; p < 8; p++) {
        *reinterpret_cast<float4*>(&sm[w * 1024 + p * 128 + lane * 4]) =
            make_float4(acc[p * 4 + 0], acc[p * 4 + 1], acc[p * 4 + 2], acc[p * 4 + 3]);
    }
    __syncthreads();
    int t = threadIdx.x;
    int jmax = npass << 7;
    #pragma unroll
    for (int r = 0; r < 4; r++) {
        int j = r * 256 + t;
        if (j < jmax) {
            float s = 0.f;
            #pragma unroll
            for (int ww = 0; ww < 8; ww++) s += sm[ww * 1024 + j];
            atomicAdd(&g_sb[0][(b << 10) + j], s);
        }
    }
}

// ---------------------------------------------------------------------------
// Persistent loop: Sinkhorn steps 2..10 (stages 1..9) in one launch.
// Per-stage work-stealing over 2048 jobs (64 batches x 32-row chunks);
// counted grid barrier between stages; after stage 9, invert sb[9] in place.
// Body = R6 two-phase scalar (proven 17.6 us/pass as separate launches).
// ---------------------------------------------------------------------------
__global__ void __launch_bounds__(256, 3) persistent_kernel(const int* __restrict__ nrows,
                                                            const int* __restrict__ ncols,
                                                            int NB) {
    int lane = threadIdx.x & 31;
    int w    = threadIdx.x >> 5;
    int t    = threadIdx.x;

    __shared__ float sv[1024];        // inverted column potentials
    __shared__ float sm[8 * 1024];    // per-warp column partial staging
    __shared__ int   sjob;

    for (int stage = 1; stage <= 9; stage++) {
        while (true) {
            if (t == 0) sjob = atomicAdd(&g_jobctr[stage], 1);
            __syncthreads();
            int job = sjob;
            __syncthreads();
            if (job >= 2048) break;

            int b  = job & 63;
            int i0 = (job >> 6) << 5;
            int nr = nrows[b];
            int nc = ncols[b];
            if (i0 >= nr || nc == 0) continue;      // block-uniform
            int npass = (nc + 127) >> 7;

            // invert col sums of previous stage into smem v
            {
                const float* s_in = &g_sb[stage - 1][b << 10];
                float4 s4 = *reinterpret_cast<const float4*>(s_in + t * 4);
                float4 v4;
                v4.x = (s4.x > 0.f) ? __fdividef(1.0f, s4.x) : 0.f;
                v4.y = (s4.y > 0.f) ? __fdividef(1.0f, s4.y) : 0.f;
                v4.z = (s4.z > 0.f) ? __fdividef(1.0f, s4.z) : 0.f;
                v4.w = (s4.w > 0.f) ? __fdividef(1.0f, s4.w) : 0.f;
                *reinterpret_cast<float4*>(&sv[t * 4]) = v4;
            }
            __syncthreads();

            const __half* Kb = g_K + ((size_t)b << 20);
            int ibase = i0 + w * 4;
            int nrow  = min(4, nr - ibase);

            // phase 1: row sums
            float sums[4] = {0.f, 0.f, 0.f, 0.f};
            for (int p = 0; p < npass; p++) {
                float4 v4 = *reinterpret_cast<const float4*>(&sv[(p << 7) + (lane << 2)]);
                #pragma unroll
                for (int q = 0; q < 4; q++) {
                    if (q < nrow) {
                        uint2 kk = *reinterpret_cast<const uint2*>(
                            Kb + ((size_t)(ibase + q) << 10) + (p << 7) + (lane << 2));
                        float2 f0 = __half22float2(*reinterpret_cast<__half2*>(&kk.x));
                        float2 f1 = __half22float2(*reinterpret_cast<__half2*>(&kk.y));
                        sums[q] += fmaf(f0.x, v4.x, fmaf(f0.y, v4.y,
                                   fmaf(f1.x, v4.z, f1.y * v4.w)));
                    }
                }
            }
            float u[4];
            #pragma unroll
            for (int q = 0; q < 4; q++) {
                float s = sums[q];
                #pragma unroll
                for (int o = 16; o; o >>= 1) s += __shfl_xor_sync(0xffffffffu, s, o);
                u[q] = (s > 0.f) ? __fdividef(1.0f, s) : 0.f;
                if (lane == 0 && q < nrow) g_u[(b << 10) + ibase + q] = u[q];
            }

            // phase 2: column partials (re-read warp's own tile, L1/L2-hot)
            for (int p = 0; p < npass; p++) {
                int j = (p << 7) + (lane << 2);
                float a0 = 0.f, a1 = 0.f, a2 = 0.f, a3 = 0.f;
                #pragma unroll
                for (int q = 0; q < 4; q++) {
                    if (q < nrow) {
                        uint2 kk = *reinterpret_cast<const uint2*>(
                            Kb + ((size_t)(ibase + q) << 10) + j);
                        float2 f0 = __half22float2(*reinterpret_cast<__half2*>(&kk.x));
                        float2 f1 = __half22float2(*reinterpret_cast<__half2*>(&kk.y));
                        a0 = fmaf(f0.x, u[q], a0);
                        a1 = fmaf(f0.y, u[q], a1);
                        a2 = fmaf(f1.x, u[q], a2);
                        a3 = fmaf(f1.y, u[q], a3);
                    }
                }
                *reinterpret_cast<float4*>(&sm[w * 1024 + j]) = make_float4(a0, a1, a2, a3);
            }
            __syncthreads();

            // epilogue: cross-warp sum + global atomic
            int jmax = npass << 7;
            float* s_out = &g_sb[stage][b << 10];
            #pragma unroll
            for (int r = 0; r < 4; r++) {
                int j = r * 256 + t;
                if (j < jmax) {
                    float s = 0.f;
                    #pragma unroll
                    for (int ww = 0; ww < 8; ww++) s += sm[ww * 1024 + j];
                    atomicAdd(&s_out[j], s);
                }
            }
            __syncthreads();   // sm/sv safe to overwrite next job
        }

        // grid barrier after every stage (incl. 9 -> guards the inversion)
        __syncthreads();
        if (t == 0) {
            __threadfence();
            atomicAdd(&g_barcnt[stage], 1);
            volatile int* bp = &g_barcnt[stage];
            while (*bp < NB) __nanosleep(64);
            __threadfence();
        }
        __syncthreads();
    }

    // invert sb[9] in place: final kernel then does pure multiplies.
    for (int idx = blockIdx.x * 256 + t; idx < BB * MM; idx += NB * 256) {
        float s = g_sb[NSTAGE - 1][idx];
        g_sb[NSTAGE - 1][idx] = (s > 0.f) ? __fdividef(1.0f, s) : 0.f;
    }
}

// ---------------------------------------------------------------------------
// Final: out = valid ? u_i * exp(m_ij) * v_j : 0 (v pre-inverted in sb[9]).
// grid = 4096, block = 256, 16 float4/thread (full 256 MB write).
// ---------------------------------------------------------------------------
__global__ void final_kernel(const float* __restrict__ m,
                             const int* __restrict__ nrows,
                             const int* __restrict__ ncols,
                             float* __restrict__ out) {
    int b   = blockIdx.x >> 6;
    int sub = blockIdx.x & 63;
    int nr = nrows[b];
    int nc = ncols[b];
    const float* mb = m + ((size_t)b << 20);
    float*       ob = out + ((size_t)b << 20);
    const float* vb = &g_sb[NSTAGE - 1][b << 10];

    #pragma unroll
    for (int k = 0; k < 16; k++) {
        int q = sub * 4096 + k * 256 + threadIdx.x;
        int i = q >> 8;
        int j = (q & 255) << 2;
        float4 o;
        if (i >= nr || j >= nc) {
            o = make_float4(0.f, 0.f, 0.f, 0.f);
        } else {
            float4 mm = *reinterpret_cast<const float4*>(mb + ((size_t)q << 2));
            float  u  = g_u[(b << 10) + i];
            float4 vv = *reinterpret_cast<const float4*>(vb + j);
            // v == 0 exactly for j >= nc -> tail of boundary float4 zeroed.
            o.x = __expf(mm.x) * u * vv.x;
            o.y = __expf(mm.y) * u * vv.y;
            o.z = __expf(mm.z) * u * vv.z;
            o.w = __expf(mm.w) * u * vv.w;
        }
        *reinterpret_cast<float4*>(ob + ((size_t)q << 2)) = o;
    }
}

extern "C" void kernel_launch(void* const* d_in, const int* in_sizes, int n_in,
                              void* d_out, int out_size) {
    const float* m     = (const float*)d_in[0];
    const int*   nrows = (const int*)d_in[1];
    const int*   ncols = (const int*)d_in[2];
    float* out = (float*)d_out;

    int dev = 0;
    cudaGetDevice(&dev);
    int nsm = 0;
    cudaDeviceGetAttribute(&nsm, cudaDevAttrMultiProcessorCount, dev);
    int occ = 0;
    cudaOccupancyMaxActiveBlocksPerMultiprocessor(&occ, persistent_kernel, 256, 0);
    int NB = nsm * occ;
    if (NB > 2048) NB = 2048;
    if (NB < 1)    NB = 1;

    init_kernel<<<160, 256>>>();                                   // zero sb + counters
    build_fused_kernel<<<dim3(32, 64), 256>>>(m, nrows, ncols);    // step 1
    persistent_kernel<<<NB, 256>>>(nrows, ncols, NB);              // steps 2..10 + invert
    final_kernel<<<4096, 256>>>(m, nrows, ncols, out);
}

// round 16
// speedup vs baseline: 1.1325x; 1.1325x over previous
#include <cuda_runtime.h>
#include <cuda_fp16.h>
#include <cstdint>

// Sinkhorn, linear domain, fp16-compressed kernel matrix, stage-buffered
// column sums (no per-iteration sync kernel, no fences, no init kernel):
//   K = valid ? fp16(exp(m)) : 0      (built fused with Sinkhorn step 1, v0=1)
//   step t: u_i = 1 / sum_j K_ij * inv(sb[t-1]_j) ; sb[t]_j += sum_i K_ij u_i
//   out = valid ? u_i * exp(m_ij) * inv(sb[9]_j) : 0   (fp32 exp recompute)
// B=64, N=1024, M=1024, tau=1, 10 steps. inv(s) = s>0 ? 1/s : 0 (s==0 exactly
// for invalid columns since only zeros are ever accumulated there).
//
// Stage-buffer zeroing is folded into the existing kernels (device globals
// start zero-initialized; each replay leaves the buffers zeroed for the next):
//   - build zeroes g_sb[9] (nothing touches sb[9] until fused stage 9)
//   - final zeroes g_sb[0..8] (final itself only reads sb[9])
//
// fused_pass is the R6 two-phase body (17.6 us/pass measured) with
// __launch_bounds__(256,5): 40 warps/SM instead of 32 to raise in-flight
// bytes (the pass is L2-latency-limited, not DRAM-limited, in-graph).

#define BB 64
#define NN 1024
#define MM 1024
#define NSTAGE 10

__device__ __half g_K[(size_t)BB * NN * MM];     // 128 MB scratch
__device__ float  g_u[BB * NN];
__device__ float  g_sb[NSTAGE][BB * MM];         // per-stage col-sum buffers

// ---------------------------------------------------------------------------
// Build + Sinkhorn step 1 (v0 = 1): block = 32 rows x 8 warps x 4 rows.
// Also zeroes this block's slice of g_sb[9] for the NEXT replay (done before
// the early-exit so every block contributes). grid = (32, 64), block = 256.
// ---------------------------------------------------------------------------
__global__ void __launch_bounds__(256) build_fused_kernel(const float* __restrict__ m,
                                                          const int* __restrict__ nrows,
                                                          const int* __restrict__ ncols) {
    int b  = blockIdx.y;
    // zero sb[9] slice (32 floats per block; safe: sb[9] untouched until stage 9)
    if (threadIdx.x < 32)
        g_sb[NSTAGE - 1][(b << 10) + blockIdx.x * 32 + threadIdx.x] = 0.f;

    int nr = nrows[b];
    int nc = ncols[b];
    int i0 = blockIdx.x * 32;
    if (i0 >= nr || nc == 0) return;
    int npass = (nc + 127) >> 7;   // 128-col tiles

    int lane = threadIdx.x & 31;
    int w    = threadIdx.x >> 5;

    float acc[32];
    #pragma unroll
    for (int k = 0; k < 32; k++) acc[k] = 0.f;

    const float* mb = m + ((size_t)b << 20);
    __half*      Kb = g_K + ((size_t)b << 20);

    #pragma unroll
    for (int q = 0; q < 4; q++) {
        int i = i0 + w * 4 + q;
        if (i < nr) {
            const float* mrow = mb + ((size_t)i << 10);
            __half*      krow = Kb + ((size_t)i << 10);
            uint2 kk[8];
            float s0 = 0.f, s1 = 0.f, s2 = 0.f, s3 = 0.f;
            #pragma unroll
            for (int p = 0; p < 8; p++) {
                if (p < npass) {
                    int j = p * 128 + lane * 4;
                    float4 mv = *reinterpret_cast<const float4*>(mrow + j);
                    float e0 = (j + 0 < nc) ? __expf(mv.x) : 0.f;
                    float e1 = (j + 1 < nc) ? __expf(mv.y) : 0.f;
                    float e2 = (j + 2 < nc) ? __expf(mv.z) : 0.f;
                    float e3 = (j + 3 < nc) ? __expf(mv.w) : 0.f;
                    __half2 h0 = __floats2half2_rn(e0, e1);
                    __half2 h1 = __floats2half2_rn(e2, e3);
                    kk[p].x = *reinterpret_cast<uint32_t*>(&h0);
                    kk[p].y = *reinterpret_cast<uint32_t*>(&h1);
                    *reinterpret_cast<uint2*>(krow + j) = kk[p];
                } else {
                    kk[p] = make_uint2(0u, 0u);
                }
                float2 f0 = __half22float2(*reinterpret_cast<__half2*>(&kk[p].x));
                float2 f1 = __half22float2(*reinterpret_cast<__half2*>(&kk[p].y));
                s0 += f0.x; s1 += f0.y; s2 += f1.x; s3 += f1.y;   // v0 = 1
            }
            float sum = (s0 + s1) + (s2 + s3);
            #pragma unroll
            for (int o = 16; o; o >>= 1) sum += __shfl_xor_sync(0xffffffffu, sum, o);
            float u = (sum > 0.f) ? __fdividef(1.0f, sum) : 0.f;
            if (lane == 0) g_u[(b << 10) + i] = u;
            #pragma unroll
            for (int p = 0; p < 8; p++) {
                float2 f0 = __half22float2(*reinterpret_cast<__half2*>(&kk[p].x));
                float2 f1 = __half22float2(*reinterpret_cast<__half2*>(&kk[p].y));
                acc[p * 4 + 0] = fmaf(f0.x, u, acc[p * 4 + 0]);
                acc[p * 4 + 1] = fmaf(f0.y, u, acc[p * 4 + 1]);
                acc[p * 4 + 2] = fmaf(f1.x, u, acc[p * 4 + 2]);
                acc[p * 4 + 3] = fmaf(f1.y, u, acc[p * 4 + 3]);
            }
        }
    }
    // epilogue
    __shared__ float sm[8 * 1024];
    #pragma unroll
    for (int p = 0; p < 8; p++) {
        *reinterpret_cast<float4*>(&sm[w * 1024 + p * 128 + lane * 4]) =
            make_float4(acc[p * 4 + 0], acc[p * 4 + 1], acc[p * 4 + 2], acc[p * 4 + 3]);
    }
    __syncthreads();
    int t = threadIdx.x;
    int jmax = npass << 7;
    #pragma unroll
    for (int r = 0; r < 4; r++) {
        int j = r * 256 + t;
        if (j < jmax) {
            float s = 0.f;
            #pragma unroll
            for (int ww = 0; ww < 8; ww++) s += sm[ww * 1024 + j];
            atomicAdd(&g_sb[0][(b << 10) + j], s);
        }
    }
}

// ---------------------------------------------------------------------------
// Fused Sinkhorn step `stage` (1..9), two-phase low-register version:
//   prologue: invert sb[stage-1] into smem v (4 KB, lane*4 conflict-free)
//   phase 1: row sums from K (4 rows per warp) against smem v -> u[4]
//   phase 2: re-read warp's own 8 KB K tile (L1/L2-hot), fma with u, stage
//     per-tile partials to per-warp smem row
//   epilogue: cross-warp smem sum, one atomicAdd per column into sb[stage].
// grid = (32, 64), block = 256, 5 CTAs/SM (40 warps: latency-limited pass).
// ---------------------------------------------------------------------------
__global__ void __launch_bounds__(256, 5) fused_pass_kernel(const int* __restrict__ nrows,
                                                            const int* __restrict__ ncols,
                                                            int stage) {
    int b  = blockIdx.y;
    int nr = nrows[b];
    int nc = ncols[b];
    int i0 = blockIdx.x * 32;
    if (i0 >= nr || nc == 0) return;
    int npass = (nc + 127) >> 7;      // 128-col tiles

    int lane = threadIdx.x & 31;
    int w    = threadIdx.x >> 5;
    int t    = threadIdx.x;

    __shared__ float sv[1024];        // inverted column potentials
    __shared__ float sm[8 * 1024];    // per-warp column partial staging

    {
        const float* s_in = &g_sb[stage - 1][b << 10];
        float4 s4 = *reinterpret_cast<const float4*>(s_in + t * 4);
        float4 v4;
        v4.x = (s4.x > 0.f) ? __fdividef(1.0f, s4.x) : 0.f;
        v4.y = (s4.y > 0.f) ? __fdividef(1.0f, s4.y) : 0.f;
        v4.z = (s4.z > 0.f) ? __fdividef(1.0f, s4.z) : 0.f;
        v4.w = (s4.w > 0.f) ? __fdividef(1.0f, s4.w) : 0.f;
        *reinterpret_cast<float4*>(&sv[t * 4]) = v4;
    }
    __syncthreads();

    const __half* Kb = g_K + ((size_t)b << 20);
    int ibase = i0 + w * 4;
    int nrow  = min(4, nr - ibase);   // may be <= 0; warp still does smem duties

    // ---- phase 1: row sums ----
    float sums[4] = {0.f, 0.f, 0.f, 0.f};
    for (int p = 0; p < npass; p++) {
        float4 v4 = *reinterpret_cast<const float4*>(&sv[(p << 7) + (lane << 2)]);
        #pragma unroll
        for (int q = 0; q < 4; q++) {
            if (q < nrow) {
                uint2 kk = *reinterpret_cast<const uint2*>(
                    Kb + ((size_t)(ibase + q) << 10) + (p << 7) + (lane << 2));
                float2 f0 = __half22float2(*reinterpret_cast<__half2*>(&kk.x));
                float2 f1 = __half22float2(*reinterpret_cast<__half2*>(&kk.y));
                float s = fmaf(f0.x, v4.x, fmaf(f0.y, v4.y,
                          fmaf(f1.x, v4.z, f1.y * v4.w)));
                sums[q] += s;
            }
        }
    }
    float u[4];
    #pragma unroll
    for (int q = 0; q < 4; q++) {
        float s = sums[q];
        #pragma unroll
        for (int o = 16; o; o >>= 1) s += __shfl_xor_sync(0xffffffffu, s, o);
        u[q] = (s > 0.f) ? __fdividef(1.0f, s) : 0.f;
        if (lane == 0 && q < nrow) g_u[(b << 10) + ibase + q] = u[q];
    }

    // ---- phase 2: column partials (re-read warp's own tile, L1/L2-hot) ----
    for (int p = 0; p < npass; p++) {
        int j = (p << 7) + (lane << 2);
        float a0 = 0.f, a1 = 0.f, a2 = 0.f, a3 = 0.f;
        #pragma unroll
        for (int q = 0; q < 4; q++) {
            if (q < nrow) {
                uint2 kk = *reinterpret_cast<const uint2*>(
                    Kb + ((size_t)(ibase + q) << 10) + j);
                float2 f0 = __half22float2(*reinterpret_cast<__half2*>(&kk.x));
                float2 f1 = __half22float2(*reinterpret_cast<__half2*>(&kk.y));
                a0 = fmaf(f0.x, u[q], a0);
                a1 = fmaf(f0.y, u[q], a1);
                a2 = fmaf(f1.x, u[q], a2);
                a3 = fmaf(f1.y, u[q], a3);
            }
        }
        *reinterpret_cast<float4*>(&sm[w * 1024 + j]) = make_float4(a0, a1, a2, a3);
    }
    __syncthreads();

    // ---- epilogue: cross-warp sum + global atomic ----
    int jmax = npass << 7;
    float* s_out = &g_sb[stage][b << 10];
    #pragma unroll
    for (int r = 0; r < 4; r++) {
        int j = r * 256 + t;
        if (j < jmax) {
            float s = 0.f;
            #pragma unroll
            for (int ww = 0; ww < 8; ww++) s += sm[ww * 1024 + j];
            atomicAdd(&s_out[j], s);
        }
    }
}

// ---------------------------------------------------------------------------
// Final: out = valid ? u_i * exp(m_ij) * inv(sb[9]_j) : 0 — fp32 exp.
// Also re-zeroes g_sb[0..8] for the next graph replay (final only reads
// sb[9], so no reader conflict). grid = 4096, block = 256.
// ---------------------------------------------------------------------------
__global__ void final_kernel(const float* __restrict__ m,
                             const int* __restrict__ nrows,
                             const int* __restrict__ ncols,
                             float* __restrict__ out) {
    // zero sb[0..8] (9*65536 floats across 4096 blocks; <=1 store per thread)
    {
        int z = blockIdx.x * 256 + threadIdx.x;
        const int ztot = (NSTAGE - 1) * BB * MM;
        if (z < ztot) (&g_sb[0][0])[z] = 0.f;
    }

    int b   = blockIdx.x >> 6;
    int sub = blockIdx.x & 63;
    int nr = nrows[b];
    int nc = ncols[b];
    const float* mb = m + ((size_t)b << 20);
    float*       ob = out + ((size_t)b << 20);
    const float* sb = &g_sb[NSTAGE - 1][b << 10];

    #pragma unroll
    for (int k = 0; k < 16; k++) {
        int q = sub * 4096 + k * 256 + threadIdx.x;  // float4 index in batch
        int i = q >> 8;
        int j = (q & 255) << 2;
        float4 o;
        if (i >= nr || j >= nc) {
            o = make_float4(0.f, 0.f, 0.f, 0.f);
        } else {
            float4 mm = *reinterpret_cast<const float4*>(mb + ((size_t)q << 2));
            float  u  = g_u[(b << 10) + i];
            float4 s4 = *reinterpret_cast<const float4*>(sb + j);
            float vx = (s4.x > 0.f) ? __fdividef(1.0f, s4.x) : 0.f;
            float vy = (s4.y > 0.f) ? __fdividef(1.0f, s4.y) : 0.f;
            float vz = (s4.z > 0.f) ? __fdividef(1.0f, s4.z) : 0.f;
            float vw = (s4.w > 0.f) ? __fdividef(1.0f, s4.w) : 0.f;
            // s==0 exactly for j >= nc, so tail elements of a boundary
            // float4 are zeroed automatically (exp(m) is finite).
            o.x = __expf(mm.x) * u * vx;
            o.y = __expf(mm.y) * u * vy;
            o.z = __expf(mm.z) * u * vz;
            o.w = __expf(mm.w) * u * vw;
        }
        *reinterpret_cast<float4*>(ob + ((size_t)q << 2)) = o;
    }
}

extern "C" void kernel_launch(void* const* d_in, const int* in_sizes, int n_in,
                              void* d_out, int out_size) {
    const float* m     = (const float*)d_in[0];
    const int*   nrows = (const int*)d_in[1];
    const int*   ncols = (const int*)d_in[2];
    float* out = (float*)d_out;

    build_fused_kernel<<<dim3(32, 64), 256>>>(m, nrows, ncols);    // step 1 (+zero sb[9])
    for (int t = 1; t <= 9; t++)                                   // steps 2..10
        fused_pass_kernel<<<dim3(32, 64), 256>>>(nrows, ncols, t);
    final_kernel<<<4096, 256>>>(m, nrows, ncols, out);             // out (+zero sb[0..8])
}